// round 11
// baseline (speedup 1.0000x reference)
#include <cuda_runtime.h>

// OTTT step: s, u_new = LIF(sig_tau*u + x@W + b); a_hat_new = sig_tau*a_hat + x
// Inputs (metadata order): W [8192*8192] f32, b [8192], u [8192], a_hat [8192], x [8192]
// Output: flat [s(8192) | u_new(8192) | a_hat_new(8192)] f32
//
// Single kernel, full-K per CTA, 512 CTAs x 16 columns. No split-K partials,
// no grid sync, no second kernel: each CTA reduces its own 64 phase-partials
// in smem (fixed order) and applies the fused LIF epilogue. 512 CTAs is the
// measured bandwidth-optimal grid for this chip (R2/R10: 6.8 TB/s).

#define IN_DIM  8192
#define OUT_DIM 8192
#define TPB     256
#define CW      16                         // columns per CTA
#define C4W     (CW / 4)                   // 4 float4 columns per CTA
#define PHASES  64                         // row phases (threads per column)
#define RPT     (IN_DIM / PHASES)          // 128 rows per thread
#define NBLK    (OUT_DIM / CW)             // 512 CTAs

// sigmoid(2.0)
#define SIG_TAU 0.8807970779778823f
#define V_TH    1.0f

__global__ void __launch_bounds__(TPB, 4) ottt_step(
    const float* __restrict__ W, const float* __restrict__ x,
    const float* __restrict__ b, const float* __restrict__ u,
    const float* __restrict__ a_hat, float* __restrict__ out)
{
    const int t  = threadIdx.x;
    const int c  = t & (C4W - 1);          // float4 column 0..3
    const int g  = t >> 2;                 // row phase 0..63
    const int c4 = blockIdx.x * C4W + c;   // global float4 column index

    __shared__ float  xs[IN_DIM];          // 32 KB
    __shared__ float4 red[PHASES][C4W];    // 4 KB

    // stage x once (coalesced float4)
    {
        const float4* __restrict__ xv4 = reinterpret_cast<const float4*>(x);
        float4* __restrict__ xs4 = reinterpret_cast<float4*>(xs);
        #pragma unroll
        for (int i = 0; i < IN_DIM / 4 / TPB; ++i)
            xs4[t + i * TPB] = xv4[t + i * TPB];
    }
    __syncthreads();

    // main loop: thread (c,g) accumulates rows g, g+64, g+128, ...
    const float4* __restrict__ Wv = reinterpret_cast<const float4*>(W);
    const size_t row_v4 = OUT_DIM / 4;

    float ax = 0.f, ay = 0.f, az = 0.f, aw = 0.f;

    #pragma unroll 8
    for (int k = 0; k < RPT; ++k) {
        const int r = g + k * PHASES;
        // streaming load: W never reused — evict-first in L2
        float4 w = __ldcs(Wv + (size_t)r * row_v4 + c4);
        float xv = xs[r];
        ax = fmaf(xv, w.x, ax);
        ay = fmaf(xv, w.y, ay);
        az = fmaf(xv, w.z, az);
        aw = fmaf(xv, w.w, aw);
    }

    red[g][c] = make_float4(ax, ay, az, aw);
    __syncthreads();

    // stage 1: 64 -> 8 partials per column (fixed order => deterministic)
    if (t < 32) {
        const int cc = t & (C4W - 1);
        const int h  = t >> 2;             // 0..7
        float4 s0 = red[h][cc];
        #pragma unroll
        for (int k = 1; k < 8; ++k) {
            float4 p = red[h + 8 * k][cc];
            s0.x += p.x; s0.y += p.y; s0.z += p.z; s0.w += p.w;
        }
        red[h][cc] = s0;
    }
    __syncthreads();

    // stage 2 + fused epilogue
    if (t < C4W) {
        // one thread per float4 column: final 8-way sum + LIF
        float4 acc = red[0][t];
        #pragma unroll
        for (int h = 1; h < 8; ++h) {
            float4 p = red[h][t];
            acc.x += p.x; acc.y += p.y; acc.z += p.z; acc.w += p.w;
        }

        const int cg = blockIdx.x * C4W + t;
        const float4 bv = reinterpret_cast<const float4*>(b)[cg];
        const float4 uv = reinterpret_cast<const float4*>(u)[cg];

        float4 upre, sv, unew;
        upre.x = fmaf(SIG_TAU, uv.x, acc.x + bv.x);
        upre.y = fmaf(SIG_TAU, uv.y, acc.y + bv.y);
        upre.z = fmaf(SIG_TAU, uv.z, acc.z + bv.z);
        upre.w = fmaf(SIG_TAU, uv.w, acc.w + bv.w);
        sv.x = (upre.x >= V_TH) ? 1.0f : 0.0f;
        sv.y = (upre.y >= V_TH) ? 1.0f : 0.0f;
        sv.z = (upre.z >= V_TH) ? 1.0f : 0.0f;
        sv.w = (upre.w >= V_TH) ? 1.0f : 0.0f;
        unew.x = upre.x - sv.x * V_TH;
        unew.y = upre.y - sv.y * V_TH;
        unew.z = upre.z - sv.z * V_TH;
        unew.w = upre.w - sv.w * V_TH;

        reinterpret_cast<float4*>(out)[cg]           = sv;
        reinterpret_cast<float4*>(out + OUT_DIM)[cg] = unew;
    } else if (t < 2 * C4W) {
        // a_hat_new = sig_tau*a_hat + x (IN_DIM == OUT_DIM; x staged in xs)
        const int tt = t - C4W;
        const int cg = blockIdx.x * C4W + tt;
        const float4 av = reinterpret_cast<const float4*>(a_hat)[cg];
        const float4 xv = reinterpret_cast<const float4*>(xs)[cg];
        float4 an;
        an.x = fmaf(SIG_TAU, av.x, xv.x);
        an.y = fmaf(SIG_TAU, av.y, xv.y);
        an.z = fmaf(SIG_TAU, av.z, xv.z);
        an.w = fmaf(SIG_TAU, av.w, xv.w);
        reinterpret_cast<float4*>(out + 2 * OUT_DIM)[cg] = an;
    }
}

extern "C" void kernel_launch(void* const* d_in, const int* in_sizes, int n_in,
                              void* d_out, int out_size)
{
    const float* W     = (const float*)d_in[0];
    const float* b     = (const float*)d_in[1];
    const float* u     = (const float*)d_in[2];
    const float* a_hat = (const float*)d_in[3];
    const float* x     = (const float*)d_in[4];
    float* out = (float*)d_out;

    ottt_step<<<NBLK, TPB>>>(W, x, b, u, a_hat, out);
}

// round 12
// speedup vs baseline: 1.1453x; 1.1453x over previous
#include <cuda_runtime.h>

// OTTT step: s, u_new = LIF(sig_tau*u + x@W + b); a_hat_new = sig_tau*a_hat + x
// Inputs (metadata order): W [8192*8192] f32, b [8192], u [8192], a_hat [8192], x [8192]
// Output: flat [s(8192) | u_new(8192) | a_hat_new(8192)] f32
//
// Split-K GEMV (proven 6.8 TB/s shape). Cross-split reduction is done with
// DETERMINISTIC int64 fixed-point atomics (integer add commutes exactly, so
// the sum is bit-identical regardless of CTA completion order). No 2MB float
// partial array, no DRAM round-trip: the 64KB accumulator lives in L2 where
// the atomics resolve. Tiny PDL epilogue converts back + LIF.

#define IN_DIM  8192
#define OUT_DIM 8192
#define SPLITS  64
#define ROWS_PER_SPLIT (IN_DIM / SPLITS)   // 128
#define TPB     256
#define JPT     4                          // columns per thread (float4)
#define JPB     (TPB * JPT)                // 1024 columns per block
#define JBLOCKS (OUT_DIM / JPB)            // 8

// sigmoid(2.0)
#define SIG_TAU 0.8807970779778823f
#define V_TH    1.0f

// fixed-point scale 2^42: |partial| < ~1, sum of 64 -> far below int64 range;
// quantization 2^-42 per term -> ~1e-11 total, invisible at 1e-3 tolerance.
#define FP_SCALE    4398046511104.0        // 2^42
#define FP_INVSCALE (1.0 / 4398046511104.0)

// 64KB fixed-point accumulator. Zero at load; epilogue resets after reading,
// so every graph replay starts from zero (deterministic).
__device__ unsigned long long g_acc[OUT_DIM];

__global__ void __launch_bounds__(TPB) gemv_partial(
    const float* __restrict__ W, const float* __restrict__ x)
{
    const int jb    = blockIdx.x;           // 0..7
    const int split = blockIdx.y;           // 0..63
    const int j0    = jb * JPB + threadIdx.x * JPT;
    const int i0    = split * ROWS_PER_SPLIT;

    __shared__ float xs[ROWS_PER_SPLIT];
    for (int t = threadIdx.x; t < ROWS_PER_SPLIT; t += TPB)
        xs[t] = x[i0 + t];
    __syncthreads();

    const float4* __restrict__ Wv =
        reinterpret_cast<const float4*>(W + (size_t)i0 * OUT_DIM + j0);
    const size_t row_v4 = OUT_DIM / 4;

    float ax = 0.f, ay = 0.f, az = 0.f, aw = 0.f;

    #pragma unroll 8
    for (int r = 0; r < ROWS_PER_SPLIT; ++r) {
        // streaming load: W is 268MB, never reused — evict-first in L2
        float4 w = __ldcs(Wv + (size_t)r * row_v4);
        float xv = xs[r];
        ax = fmaf(xv, w.x, ax);
        ay = fmaf(xv, w.y, ay);
        az = fmaf(xv, w.z, az);
        aw = fmaf(xv, w.w, aw);
    }

    // deterministic reduction: exact int64 adds commute; f32->f64->ll is
    // exact up to the 2^-42 quantum (double mult by a power of two is exact).
    long long q0 = __double2ll_rn((double)ax * FP_SCALE);
    long long q1 = __double2ll_rn((double)ay * FP_SCALE);
    long long q2 = __double2ll_rn((double)az * FP_SCALE);
    long long q3 = __double2ll_rn((double)aw * FP_SCALE);
    atomicAdd(&g_acc[j0 + 0], (unsigned long long)q0);
    atomicAdd(&g_acc[j0 + 1], (unsigned long long)q1);
    atomicAdd(&g_acc[j0 + 2], (unsigned long long)q2);
    atomicAdd(&g_acc[j0 + 3], (unsigned long long)q3);

    // let the PDL epilogue start launching/prefetching while we drain
    cudaTriggerProgrammaticLaunchCompletion();
}

// Epilogue (PDL secondary): 8192 threads, one output column each.
// Pre-sync: a_hat trace (GEMV-independent). Post-sync: read L2-hot 64KB
// accumulator, convert, LIF, and reset the accumulator for the next replay.
#define EPI_TPB    256
#define EPI_BLOCKS (OUT_DIM / EPI_TPB)     // 32

__global__ void __launch_bounds__(EPI_TPB) lif_epilogue(
    const float* __restrict__ b, const float* __restrict__ u,
    const float* __restrict__ a_hat, const float* __restrict__ x,
    float* __restrict__ out)
{
    const int j = blockIdx.x * EPI_TPB + threadIdx.x;

    // ---- GEMV-independent work before waiting ----
    const float bj = b[j];
    const float uj = u[j];
    out[2 * OUT_DIM + j] = fmaf(SIG_TAU, a_hat[j], x[j]);   // a_hat_new

    // ---- wait for the GEMV grid's atomics to be visible ----
    cudaGridDependencySynchronize();

    const long long q = (long long)g_acc[j];
    g_acc[j] = 0ULL;                        // sole reader: reset for replay

    const float acc   = (float)((double)q * FP_INVSCALE);
    const float u_pre = fmaf(SIG_TAU, uj, acc + bj);
    const float spike = (u_pre >= V_TH) ? 1.0f : 0.0f;

    out[j]           = spike;
    out[OUT_DIM + j] = u_pre - spike * V_TH;
}

extern "C" void kernel_launch(void* const* d_in, const int* in_sizes, int n_in,
                              void* d_out, int out_size)
{
    const float* W     = (const float*)d_in[0];
    const float* b     = (const float*)d_in[1];
    const float* u     = (const float*)d_in[2];
    const float* a_hat = (const float*)d_in[3];
    const float* x     = (const float*)d_in[4];
    float* out = (float*)d_out;

    dim3 grid(JBLOCKS, SPLITS);
    gemv_partial<<<grid, TPB>>>(W, x);

    // PDL secondary: may launch while gemv_partial drains.
    cudaLaunchConfig_t cfg = {};
    cfg.gridDim  = dim3(EPI_BLOCKS, 1, 1);
    cfg.blockDim = dim3(EPI_TPB, 1, 1);
    cfg.dynamicSmemBytes = 0;
    cfg.stream = 0;
    cudaLaunchAttribute attr[1];
    attr[0].id = cudaLaunchAttributeProgrammaticStreamSerialization;
    attr[0].val.programmaticStreamSerializationAllowed = 1;
    cfg.attrs = attr;
    cfg.numAttrs = 1;
    cudaLaunchKernelEx(&cfg, lif_epilogue, b, u, a_hat, x, out);
}